// round 5
// baseline (speedup 1.0000x reference)
#include <cuda_runtime.h>
#include <cuda_bf16.h>

#define FULL_MASK 0xFFFFFFFFu

constexpr int B_ROWS     = 16384;
constexpr int SEQ_L      = 50;
constexpr int N_ITER     = 7;        // 7 * 8 groups = 56 >= 50 positions
constexpr int N_SUBJECTS = 10000;
constexpr int ROWS_PER_BLOCK = 32;   // 8 warps x 4 rows each
constexpr int THREADS    = 256;

// Per-subject exp(score) = exp(dot(emb[j], w) + b). Softmax without
// max-subtraction is exact here: scores are O(0.1) (emb ~0.1*N, w ~0.25*N,
// D=16), no fp32 overflow risk; softmax is shift-invariant.
__device__ float g_escore[N_SUBJECTS];

__device__ __forceinline__ float dot4(float4 a, float4 b) {
    return a.x * b.x + a.y * b.y + a.z * b.z + a.w * b.w;
}

// ---------------- Prologue: build the exp(score) table ----------------
__global__ void __launch_bounds__(256)
escore_kernel(const float* __restrict__ subj_emb,
              const float* __restrict__ attn_w,
              const float* __restrict__ attn_b)
{
    const int j = blockIdx.x * blockDim.x + threadIdx.x;
    if (j >= N_SUBJECTS) return;

    const float4* wp = reinterpret_cast<const float4*>(attn_w);
    const float4 w0 = __ldg(wp + 0), w1 = __ldg(wp + 1),
                 w2 = __ldg(wp + 2), w3 = __ldg(wp + 3);

    const float4* ep = reinterpret_cast<const float4*>(subj_emb) + (size_t)j * 4;
    const float s = dot4(__ldg(ep + 0), w0) + dot4(__ldg(ep + 1), w1)
                  + dot4(__ldg(ep + 2), w2) + dot4(__ldg(ep + 3), w3)
                  + __ldg(attn_b);
    g_escore[j] = __expf(s);
}

// ---------------- Main kernel ----------------
// Warp = 8 groups x 4 lanes. Group g handles positions p = it*8+g; lane
// chunk c = lane&3 owns 16B of the 64B emb row (4 lanes of a group hit the
// same 128B line). escore served from a block-shared 40KB table.
__global__ void __launch_bounds__(THREADS)
scalar_pooler_kernel(
    const float* __restrict__ subj_emb,
    const float* __restrict__ user_bias,
    const float* __restrict__ item_bias,
    const float* __restrict__ global_bias,
    const int*   __restrict__ user_idx,
    const int*   __restrict__ item_idx,
    const int*   __restrict__ fav,
    const int*   __restrict__ book,
    float*       __restrict__ out)
{
    __shared__ float s_escore[N_SUBJECTS];

    // Fill escore table (coalesced float4 loads from the device-global table).
    {
        const float4* src = reinterpret_cast<const float4*>(g_escore);
        float4* dst = reinterpret_cast<float4*>(s_escore);
        #pragma unroll
        for (int i = threadIdx.x; i < N_SUBJECTS / 4; i += THREADS)
            dst[i] = __ldg(src + i);
    }
    __syncthreads();

    const int warp  = threadIdx.x >> 5;
    const int lane  = threadIdx.x & 31;
    const int grp   = lane >> 2;
    const int chunk = lane & 3;

    const float4* emb = reinterpret_cast<const float4*>(subj_emb);
    const int row0 = blockIdx.x * ROWS_PER_BLOCK + warp * (ROWS_PER_BLOCK / 8);

    #pragma unroll
    for (int r = 0; r < ROWS_PER_BLOCK / 8; r++) {
        const int row = row0 + r;
        const int* frow = fav  + (size_t)row * SEQ_L;
        const int* brow = book + (size_t)row * SEQ_L;

        float4 au = make_float4(0.f, 0.f, 0.f, 0.f);
        float4 ai = make_float4(0.f, 0.f, 0.f, 0.f);
        float  su = 0.f, si = 0.f;

        #pragma unroll
        for (int it = 0; it < N_ITER; it++) {
            const int  p     = it * 8 + grp;
            const bool valid = (p < SEQ_L);          // compile-time for it<6

            // 4 lanes of a group read the same idx address -> broadcast.
            const int iu = valid ? __ldg(frow + p) : 0;
            const int ib = valid ? __ldg(brow + p) : 0;

            float4 eu = make_float4(0.f, 0.f, 0.f, 0.f);
            float4 eb = eu;
            if (valid) {
                eu = __ldg(emb + (size_t)iu * 4 + chunk);
                eb = __ldg(emb + (size_t)ib * 4 + chunk);
            }
            const float wu = (valid && iu != 0) ? s_escore[iu] : 0.f;
            const float wb = (valid && ib != 0) ? s_escore[ib] : 0.f;

            su += wu;  si += wb;
            au.x = fmaf(wu, eu.x, au.x);  au.y = fmaf(wu, eu.y, au.y);
            au.z = fmaf(wu, eu.z, au.z);  au.w = fmaf(wu, eu.w, au.w);
            ai.x = fmaf(wb, eb.x, ai.x);  ai.y = fmaf(wb, eb.y, ai.y);
            ai.z = fmaf(wb, eb.z, ai.z);  ai.w = fmaf(wb, eb.w, ai.w);
        }

        // Reduce denominators across the 8 groups (strides 4,8,16).
        #pragma unroll
        for (int off = 4; off < 32; off <<= 1) {
            su += __shfl_xor_sync(FULL_MASK, su, off);
            si += __shfl_xor_sync(FULL_MASK, si, off);
        }

        // Fully reduce u's chunk across groups; ai stays per-lane partial.
        #pragma unroll
        for (int off = 4; off < 32; off <<= 1) {
            au.x += __shfl_xor_sync(FULL_MASK, au.x, off);
            au.y += __shfl_xor_sync(FULL_MASK, au.y, off);
            au.z += __shfl_xor_sync(FULL_MASK, au.z, off);
            au.w += __shfl_xor_sync(FULL_MASK, au.w, off);
        }

        // All-pad row: reference pools the zero row -> inv = 0 matches exactly.
        const float inv_u = (su > 0.f) ? (1.0f / su) : 0.f;
        const float inv_i = (si > 0.f) ? (1.0f / si) : 0.f;

        // dot(u, i): lane contributes dot(u_chunk[c], ai_partial[c, g]);
        // the 32-lane sum counts each (chunk, group) cell exactly once.
        float p = dot4(au, ai);
        #pragma unroll
        for (int off = 16; off; off >>= 1)
            p += __shfl_xor_sync(FULL_MASK, p, off);

        if (lane == 0) {
            out[row] = p * inv_u * inv_i
                     + __ldg(user_bias + __ldg(user_idx + row))
                     + __ldg(item_bias + __ldg(item_idx + row))
                     + __ldg(global_bias);
        }
    }
}

extern "C" void kernel_launch(void* const* d_in, const int* in_sizes, int n_in,
                              void* d_out, int out_size)
{
    const float* subj_emb    = (const float*)d_in[0];
    const float* attn_w      = (const float*)d_in[1];
    const float* attn_b      = (const float*)d_in[2];
    const float* user_bias   = (const float*)d_in[3];
    const float* item_bias   = (const float*)d_in[4];
    const float* global_bias = (const float*)d_in[5];
    const int*   user_idx    = (const int*)d_in[6];
    const int*   item_idx    = (const int*)d_in[7];
    const int*   fav         = (const int*)d_in[8];
    const int*   book        = (const int*)d_in[9];
    float*       out         = (float*)d_out;

    escore_kernel<<<(N_SUBJECTS + 255) / 256, 256>>>(subj_emb, attn_w, attn_b);

    const int blocks = B_ROWS / ROWS_PER_BLOCK;    // 512
    scalar_pooler_kernel<<<blocks, THREADS>>>(
        subj_emb, user_bias, item_bias, global_bias,
        user_idx, item_idx, fav, book, out);
}